// round 8
// baseline (speedup 1.0000x reference)
#include <cuda_runtime.h>
#include <cstdint>

// SIR RK4, scalar fp32, TWO independent batch elements per thread
// (32768 threads, 1024 warps). Scalar FFMA lat=4: the second element's chain
// statically fills the first's RAW gaps inside one warp (intra-warp ILP),
// which the Round-7 1-elem/thread version lacked (fma 31%, issue 42%,
// latency-bound). Packed f32x2 was abandoned in R5: measured dependent
// latency ~13-15cyc made ILP there ineffective.
// State per element: a = (h/2)*beta*S, v = beta*I -> 21 FFMA-class ops per
// substep (7 immediate-form), 4 substeps per saved step.
// R recovered from the RK4-preserved invariant R = 1 - S - I.
__global__ void __launch_bounds__(64) sir_rk4(const float* __restrict__ params,
                                              float* __restrict__ out, int n)
{
    const int gid = blockIdx.x * 64 + threadIdx.x;
    const int b0 = gid * 2;
    if (b0 + 1 >= n) return;

    const float4 pA = reinterpret_cast<const float4*>(params)[b0];
    const float4 pB = reinterpret_cast<const float4*>(params)[b0 + 1];

    constexpr float H  = (100.0f / 199.0f) / 4.0f;  // substep size
    constexpr float H2 = 0.5f * H;
    constexpr float H6 = H / 6.0f;

    const float betaA = fmaxf(pA.x, 1e-20f);
    const float betaB = fmaxf(pB.x, 1e-20f);
    const float gA = pA.y, gB = pB.y;

    // per-element coefficients
    const float c1A   = 1.0f - H2 * gA,  c1B   = 1.0f - H2 * gB;
    const float nh2gA = -H2 * gA,        nh2gB = -H2 * gB;
    const float nhgA  = -H  * gA,        nhgB  = -H  * gB;
    const float nh6gA = -H6 * gA,        nh6gB = -H6 * gB;
    const float ibA   = 1.0f / betaA,    ibB   = 1.0f / betaB;
    const float ib2A  = 1.0f / (H2 * betaA), ib2B = 1.0f / (H2 * betaB);

    float aA = H2 * betaA * pA.z,  aB = H2 * betaB * pB.z;   // (h/2)*beta*S
    float vA = betaA * pA.w,       vB = betaB * pB.w;        // beta*I

    float4* oA = reinterpret_cast<float4*>(out + (size_t)b0 * 600);
    float4* oB = reinterpret_cast<float4*>(out + (size_t)(b0 + 1) * 600);

    // Staged results: [step-in-chunk][element].
    float fS[4][2], fI[4][2], fR[4][2];

    // One substep for BOTH elements, chains interleaved line-by-line.
    auto substep2 = [&]() {
        float p1A = aA * vA;                   float p1B = aB * vB;
        float a2A = fmaf(-H2, p1A, aA);        float a2B = fmaf(-H2, p1B, aB);
        float v2A = fmaf(c1A, vA, p1A);        float v2B = fmaf(c1B, vB, p1B);
        float p2A = a2A * v2A;                 float p2B = a2B * v2B;
        float a3A = fmaf(-H2, p2A, aA);        float a3B = fmaf(-H2, p2B, aB);
        float t3A = fmaf(nh2gA, v2A, vA);      float t3B = fmaf(nh2gB, v2B, vB);
        float v3A = t3A + p2A;                 float v3B = t3B + p2B;
        float p3A = a3A * v3A;                 float p3B = a3B * v3B;
        float a4A = fmaf(-H, p3A, aA);         float a4B = fmaf(-H, p3B, aB);
        float t4A = fmaf(nhgA, v3A, vA);       float t4B = fmaf(nhgB, v3B, vB);
        float v4A = fmaf(2.0f, p3A, t4A);      float v4B = fmaf(2.0f, p3B, t4B);
        float p4A = a4A * v4A;                 float p4B = a4B * v4B;
        float uA  = p1A + p4A;                 float uB  = p1B + p4B;
        float tA  = p2A + p3A;                 float tB  = p2B + p3B;
        float sA  = fmaf(2.0f, tA, uA);        float sB  = fmaf(2.0f, tB, uB);
        aA = fmaf(-H6, sA, aA);                aB = fmaf(-H6, sB, aB);
        float uvA = vA + v4A;                  float uvB = vB + v4B;
        float tvA = v2A + v3A;                 float tvB = v2B + v3B;
        float lvA = fmaf(2.0f, tvA, uvA);      float lvB = fmaf(2.0f, tvB, uvB);
        float nvA = fmaf(1.0f/3.0f, sA, vA);   float nvB = fmaf(1.0f/3.0f, sB, vB);
        vA = fmaf(nh6gA, lvA, nvA);            vB = fmaf(nh6gB, lvB, nvB);
    };

    auto step = [&]() {
        #pragma unroll
        for (int s = 0; s < 4; s++) substep2();
    };

    auto record = [&](int j) {
        float SA = aA * ib2A;                  float SB = aB * ib2B;
        float IA = vA * ibA;                   float IB = vB * ibB;
        fS[j][0] = SA;                         fS[j][1] = SB;
        fI[j][0] = IA;                         fI[j][1] = IB;
        fR[j][0] = 1.0f - (SA + IA);           fR[j][1] = 1.0f - (SB + IB);
    };

    auto flush = [&](int c) {
        float4* qa = oA + c * 3;
        float4* qb = oB + c * 3;
        qa[0] = make_float4(fS[0][0], fI[0][0], fR[0][0], fS[1][0]);
        qa[1] = make_float4(fI[1][0], fR[1][0], fS[2][0], fI[2][0]);
        qa[2] = make_float4(fR[2][0], fS[3][0], fI[3][0], fR[3][0]);
        qb[0] = make_float4(fS[0][1], fI[0][1], fR[0][1], fS[1][1]);
        qb[1] = make_float4(fI[1][1], fR[1][1], fS[2][1], fI[2][1]);
        qb[2] = make_float4(fR[2][1], fS[3][1], fI[3][1], fR[3][1]);
    };

    // Chunk 0: exact y0 (matching reference) + 3 integrated steps.
    fS[0][0] = pA.z;                 fS[0][1] = pB.z;
    fI[0][0] = pA.w;                 fI[0][1] = pB.w;
    fR[0][0] = (1.0f - pA.z) - pA.w; fR[0][1] = (1.0f - pB.z) - pB.w;
    #pragma unroll
    for (int j = 1; j < 4; j++) { step(); record(j); }
    flush(0);

    // Chunks 1..49: 4 integrated steps each (3 + 49*4 = 199 steps).
    #pragma unroll 1
    for (int c = 1; c < 50; c++) {
        #pragma unroll
        for (int j = 0; j < 4; j++) { step(); record(j); }
        flush(c);
    }
}

extern "C" void kernel_launch(void* const* d_in, const int* in_sizes, int n_in,
                              void* d_out, int out_size)
{
    const float* params = (const float*)d_in[0];
    float* out = (float*)d_out;
    const int n = in_sizes[0] / 4;          // batch elements (65536)
    const int nthreads = (n + 1) / 2;       // two elements per thread
    const int blocks = (nthreads + 63) / 64;
    sir_rk4<<<blocks, 64>>>(params, out, n);
}